// round 4
// baseline (speedup 1.0000x reference)
#include <cuda_runtime.h>

// ConvQuadInterp3d over x:(2,1,8,512,512) fp32.
// Output = coords_max (B,1,3,D,H,W) then y_max (B,1,D,H,W), fp32.
// One thread per (b,h,w); fully-unrolled d loop, rolling 3-plane 3x3 register
// window, separable NMS with cached column maxima, and the full quadratic-fit
// pipeline branch-gated on the (rare, ~3.7%) NMS hit.

#define Dd 8
#define Hh 512
#define Ww 512
#define Bb 2
#define PLANE (Hh * Ww)

__device__ __forceinline__ void load_plane(const float* __restrict__ x, int base,
                                           int hm, int h0, int hp,
                                           int wm, int w0, int wp,
                                           float* p, float* cm) {
    const float* r0 = x + base + hm * Ww;
    const float* r1 = x + base + h0 * Ww;
    const float* r2 = x + base + hp * Ww;
    p[0] = __ldg(r0 + wm); p[1] = __ldg(r0 + w0); p[2] = __ldg(r0 + wp);
    p[3] = __ldg(r1 + wm); p[4] = __ldg(r1 + w0); p[5] = __ldg(r1 + wp);
    p[6] = __ldg(r2 + wm); p[7] = __ldg(r2 + w0); p[8] = __ldg(r2 + wp);
    // Per-column maxima, cached for the (up to) 3 d-iterations using this plane.
    cm[0] = fmaxf(p[0], fmaxf(p[3], p[6]));
    cm[1] = fmaxf(p[1], fmaxf(p[4], p[7]));
    cm[2] = fmaxf(p[2], fmaxf(p[5], p[8]));
}

__global__ void __launch_bounds__(128, 7)
conv_quad_interp3d_kernel(const float* __restrict__ x, float* __restrict__ out) {
    const int w = blockIdx.x * 32 + threadIdx.x;
    const int h = blockIdx.y * 4 + threadIdx.y;
    const int b = blockIdx.z;

    const int wm = max(w - 1, 0), wp = min(w + 1, Ww - 1);
    const int hm = max(h - 1, 0), hp = min(h + 1, Hh - 1);
    const int xbase = b * Dd * PLANE;
    const float wf = (float)w, hf = (float)h;

    float P0[9], P1[9], P2[9];
    float cm0[3], cm1[3], cm2[3];
    load_plane(x, xbase + 0 * PLANE, hm, h, hp, wm, w, wp, P1, cm1);
#pragma unroll
    for (int i = 0; i < 9; i++) P0[i] = P1[i];
#pragma unroll
    for (int i = 0; i < 3; i++) cm0[i] = cm1[i];
    load_plane(x, xbase + 1 * PLANE, hm, h, hp, wm, w, wp, P2, cm2);

    const int hw = h * Ww + w;
    float* coordsD = out + (b * 3 + 0) * Dd * PLANE;
    float* coordsW = out + (b * 3 + 1) * Dd * PLANE;
    float* coordsH = out + (b * 3 + 2) * Dd * PLANE;
    float* ymax    = out + (Bb * 3) * Dd * PLANE + b * Dd * PLANE;

#pragma unroll
    for (int d = 0; d < Dd; d++) {
        const float c = P1[4];

        // Separable NMS: max over 27 = max over 9 cached column maxima.
        float m = fmaxf(cm0[0], fmaxf(cm0[1], cm0[2]));
        m = fmaxf(m, fmaxf(cm1[0], fmaxf(cm1[1], cm1[2])));
        m = fmaxf(m, fmaxf(cm2[0], fmaxf(cm2[1], cm2[2])));
        const bool nms = (c == m);

        // Defaults for non-maximal voxels: dx = 0, y = c, coords = grid.
        float rx = 0.0f, ry = 0.0f, rs = 0.0f;
        float y = c;

        if (nms) {  // ~3.7% of voxels; ~30% of warps skip entirely
            // Gradients (central diff / 2, replicate pad)
            const float gx = 0.5f * (P1[5] - P1[3]);
            const float gy = 0.5f * (P1[7] - P1[1]);
            const float gs = 0.5f * (P2[4] - P0[4]);

            // Hessian (cross terms * 0.25 per reference)
            const float axx = P1[3] + P1[5] - 2.0f * c;
            const float ayy = P1[1] + P1[7] - 2.0f * c;
            const float ass = P0[4] + P2[4] - 2.0f * c;
            const float axy = 0.25f * (P1[0] + P1[8] - P1[6] - P1[2]);
            const float ays = 0.25f * (P0[1] + P2[7] - P2[1] - P0[7]);
            const float axs = 0.25f * (P0[3] + P2[5] - P2[3] - P0[5]);

            // Symmetric 3x3 solve via adjugate (Cramer)
            const float c00 = ayy * ass - ays * ays;
            const float c01 = axs * ays - axy * ass;
            const float c02 = axy * ays - axs * ayy;
            const float det = axx * c00 + axy * c01 + axs * c02;

            if (det != 0.0f) {
                const float inv = 1.0f / det;
                const float c11 = axx * ass - axs * axs;
                const float c12 = axy * axs - axx * ays;
                const float c22 = axx * ayy - axy * axy;
                rx = -(c00 * gx + c01 * gy + c02 * gs) * inv;
                ry = -(c01 * gx + c11 * gy + c12 * gs) * inv;
                rs = -(c02 * gx + c12 * gy + c22 * gs) * inv;
                const float big = fmaxf(fabsf(rx), fmaxf(fabsf(ry), fabsf(rs)));
                if (big > 0.7f) { rx = 0.0f; ry = 0.0f; rs = 0.0f; }
                const float dyv = 0.5f * (gx * rx + gy * ry + gs * rs);
                y = c + dyv + 10.0f;  // strict-maxima bonus only when solved
            }
        }

        // coords channels: grid(d, w, h) + flipped refinement (s, y, x)
        const int dhw = d * PLANE + hw;
        coordsD[dhw] = (float)d + rs;
        coordsW[dhw] = wf + ry;
        coordsH[dhw] = hf + rx;
        ymax[dhw]    = y;

        if (d < Dd - 1) {
#pragma unroll
            for (int i = 0; i < 9; i++) { P0[i] = P1[i]; P1[i] = P2[i]; }
#pragma unroll
            for (int i = 0; i < 3; i++) { cm0[i] = cm1[i]; cm1[i] = cm2[i]; }
            const int dn = min(d + 2, Dd - 1);
            load_plane(x, xbase + dn * PLANE, hm, h, hp, wm, w, wp, P2, cm2);
        }
    }
}

extern "C" void kernel_launch(void* const* d_in, const int* in_sizes, int n_in,
                              void* d_out, int out_size) {
    const float* x = (const float*)d_in[0];
    float* out = (float*)d_out;
    dim3 block(32, 4, 1);
    dim3 grid(Ww / 32, Hh / 4, Bb);  // (16, 128, 2)
    conv_quad_interp3d_kernel<<<grid, block>>>(x, out);
}